// round 6
// baseline (speedup 1.0000x reference)
#include <cuda_runtime.h>
#include <cstdint>
#include <cstdio>

#define NTOK   343
#define NWIN   256
#define NHEADS 12
#define HDIM   32
#define CDIM   384
#define MROWS  (NWIN * NTOK)     // 87808
#define QKVC   (3 * CDIM)        // 1152
#define NPAD   352               // 343 padded to 11*32
#define KPAD   384               // 343 padded to 6*64

// ---------------- scratch (static device globals; no allocation allowed) ----
__device__ float g_qkv[(size_t)MROWS * QKVC];        // qkv activations
__device__ float g_att[(size_t)MROWS * CDIM];        // attention output (tf32-rounded)
__device__ float g_bias[NHEADS * NPAD * KPAD];       // padded rel-pos bias (+ -1e30 pad keys)
__device__ float g_xr[(size_t)MROWS * CDIM];         // tf32-rounded x
__device__ float g_wqt[(size_t)QKVC * CDIM];         // qkv_w transposed+rounded
__device__ float g_wpt[(size_t)CDIM * CDIM];         // proj_w transposed+rounded

// ======================= helpers ============================================
__device__ __forceinline__ float tf32_rna(float v) {
    uint32_t u;
    asm("cvt.rna.tf32.f32 %0, %1;" : "=r"(u) : "f"(v));
    return __uint_as_float(u);
}
__device__ __forceinline__ uint32_t tf32u(float v) {
    uint32_t u;
    asm("cvt.rna.tf32.f32 %0, %1;" : "=r"(u) : "f"(v));
    return u;
}
#define CP_ASYNC16(dst, src) \
    asm volatile("cp.async.cg.shared.global [%0], [%1], 16;" :: "r"(dst), "l"(src))
#define CP_COMMIT() asm volatile("cp.async.commit_group;" ::: "memory")
#define CP_WAIT1()  asm volatile("cp.async.wait_group 1;" ::: "memory")
#define CP_WAIT0()  asm volatile("cp.async.wait_group 0;" ::: "memory")

__device__ __forceinline__ uint32_t smem_u32(const void* p) {
    uint32_t a;
    asm("{ .reg .u64 t; cvta.to.shared.u64 t, %1; cvt.u32.u64 %0, t; }" : "=r"(a) : "l"(p));
    return a;
}

__device__ __forceinline__ void mma_tf32(float* c, const uint32_t* a, const uint32_t* b) {
    asm volatile(
        "mma.sync.aligned.m16n8k8.row.col.f32.tf32.tf32.f32 "
        "{%0,%1,%2,%3}, {%4,%5,%6,%7}, {%8,%9}, {%0,%1,%2,%3};"
        : "+f"(c[0]), "+f"(c[1]), "+f"(c[2]), "+f"(c[3])
        : "r"(a[0]), "r"(a[1]), "r"(a[2]), "r"(a[3]), "r"(b[0]), "r"(b[1]));
}

// ======================= prep kernels =======================================
__global__ void round_tf32_kernel(const float* __restrict__ in, float* __restrict__ out, int n4) {
    int i = blockIdx.x * blockDim.x + threadIdx.x;
    if (i < n4) {
        float4 v = reinterpret_cast<const float4*>(in)[i];
        v.x = tf32_rna(v.x); v.y = tf32_rna(v.y);
        v.z = tf32_rna(v.z); v.w = tf32_rna(v.w);
        reinterpret_cast<float4*>(out)[i] = v;
    }
}

__global__ void transpose_round_kernel(const float* __restrict__ W, float* __restrict__ Wt,
                                       int K, int Nw) {
    __shared__ float t[32][33];
    int n0 = blockIdx.x * 32, k0 = blockIdx.y * 32;
#pragma unroll
    for (int s = 0; s < 4; ++s) {
        int k = k0 + threadIdx.y + s * 8;
        t[threadIdx.y + s * 8][threadIdx.x] = tf32_rna(W[(size_t)k * Nw + n0 + threadIdx.x]);
    }
    __syncthreads();
#pragma unroll
    for (int s = 0; s < 4; ++s) {
        int n = n0 + threadIdx.y + s * 8;
        Wt[(size_t)n * K + k0 + threadIdx.x] = t[threadIdx.x][threadIdx.y + s * 8];
    }
}

// padded bias: [12][352][384]; pad keys -> -1e30 (softmax zero), pad rows -> 0
__global__ void bias_expand_pad_kernel(const float* __restrict__ bt,
                                       const int* __restrict__ ridx,
                                       float* __restrict__ bf)
{
    int idx = blockIdx.x * blockDim.x + threadIdx.x;
    if (idx < NHEADS * NPAD * KPAD) {
        int h   = idx / (NPAD * KPAD);
        int rem = idx - h * NPAD * KPAD;
        int r   = rem / KPAD;
        int k   = rem - r * KPAD;
        float v;
        if (k >= NTOK)      v = -1e30f;
        else if (r >= NTOK) v = 0.f;
        else                v = bt[ridx[r * NTOK + k] * NHEADS + h];
        bf[idx] = v;
    }
}

// ======================= mma.sync TF32 GEMM v2 ==============================
// C[M,Ntot] = A[M,384] @ Wt[Ntot,384]^T + bias.
// CTA 256x128, BK=32, 256 threads = 8 warps (4m x 2n), warp tile 64x64.
// Per warp k-step: 32 MMA / 32 LDS (ratio 1.0 vs 1.5 before); LDGSTS/output -25%.
#define GK      384
#define GNCHUNK 12
#define LDT     36
#define SM_AFL  (256 * LDT)          // floats per A stage buffer
#define SM_BFL  (128 * LDT)          // floats per B stage buffer
#define GSM_TOT ((2 * SM_AFL + 2 * SM_BFL) * 4)   // 110592 B

__global__ __launch_bounds__(256, 1) void mma_gemm_kernel(
    const float* __restrict__ A, const float* __restrict__ Wt,
    const float* __restrict__ bias, float* __restrict__ C, int Ntot)
{
    extern __shared__ float sm[];
    float* sA[2] = { sm,                sm + SM_AFL };
    float* sB[2] = { sm + 2 * SM_AFL,   sm + 2 * SM_AFL + SM_BFL };
    const uint32_t sAu[2] = { smem_u32(sA[0]), smem_u32(sA[1]) };
    const uint32_t sBu[2] = { smem_u32(sB[0]), smem_u32(sB[1]) };

    const int tid = threadIdx.x;
    const int wid = tid >> 5, lid = tid & 31;
    const int g = lid >> 2, t4 = lid & 3;
    const int wm = (wid >> 1) * 64;      // 4 m-warps
    const int wn = (wid & 1) * 64;       // 2 n-warps
    const int bm = blockIdx.y * 256;
    const int bn = blockIdx.x * 128;

    float acc[4][8][4];
#pragma unroll
    for (int i = 0; i < 4; ++i)
#pragma unroll
        for (int j = 0; j < 8; ++j)
#pragma unroll
            for (int q = 0; q < 4; ++q) acc[i][j][q] = 0.f;

    // chunk loader: A rows [bm,256) (2048 float4), B rows [bn,128) (1024 float4)
    auto load_chunk = [&](int c, int buf) {
        const float* ap = A  + (size_t)bm * GK + c * 32;
        const float* bp = Wt + (size_t)bn * GK + c * 32;
#pragma unroll
        for (int i = 0; i < 8; ++i) {
            int f = tid + i * 256;
            int row = f >> 3, c4 = (f & 7) * 4;
            CP_ASYNC16(sAu[buf] + (uint32_t)(row * LDT + c4) * 4,
                       ap + (size_t)row * GK + c4);
        }
#pragma unroll
        for (int i = 0; i < 4; ++i) {
            int f = tid + i * 256;
            int row = f >> 3, c4 = (f & 7) * 4;
            CP_ASYNC16(sBu[buf] + (uint32_t)(row * LDT + c4) * 4,
                       bp + (size_t)row * GK + c4);
        }
    };

    load_chunk(0, 0);
    CP_COMMIT();

    for (int c = 0; c < GNCHUNK; ++c) {
        const int b = c & 1;
        if (c + 1 < GNCHUNK) {
            load_chunk(c + 1, b ^ 1);
            CP_COMMIT();
            CP_WAIT1();
        } else {
            CP_WAIT0();
        }
        __syncthreads();

        const float* As = sA[b];
        const float* Bs = sB[b];
#pragma unroll
        for (int ks = 0; ks < 4; ++ks) {
            const int k = ks * 8 + t4;
            uint32_t af[4][4], bf[8][2];
#pragma unroll
            for (int mi = 0; mi < 4; ++mi) {
                const int r = wm + mi * 16 + g;
                af[mi][0] = __float_as_uint(As[r * LDT + k]);
                af[mi][1] = __float_as_uint(As[(r + 8) * LDT + k]);
                af[mi][2] = __float_as_uint(As[r * LDT + k + 4]);
                af[mi][3] = __float_as_uint(As[(r + 8) * LDT + k + 4]);
            }
#pragma unroll
            for (int ni = 0; ni < 8; ++ni) {
                const int n = wn + ni * 8 + g;
                bf[ni][0] = __float_as_uint(Bs[n * LDT + k]);
                bf[ni][1] = __float_as_uint(Bs[n * LDT + k + 4]);
            }
#pragma unroll
            for (int mi = 0; mi < 4; ++mi)
#pragma unroll
                for (int ni = 0; ni < 8; ++ni)
                    mma_tf32(acc[mi][ni], af[mi], bf[ni]);
        }
        __syncthreads();
    }

    // epilogue
#pragma unroll
    for (int mi = 0; mi < 4; ++mi) {
#pragma unroll
        for (int ni = 0; ni < 8; ++ni) {
            const int row = bm + wm + mi * 16 + g;
            const int col = bn + wn + ni * 8 + t4 * 2;
            const float b0 = __ldg(&bias[col]), b1 = __ldg(&bias[col + 1]);
            float2 v0 = { acc[mi][ni][0] + b0, acc[mi][ni][1] + b1 };
            float2 v1 = { acc[mi][ni][2] + b0, acc[mi][ni][3] + b1 };
            *reinterpret_cast<float2*>(&C[(size_t)row * Ntot + col]) = v0;
            *reinterpret_cast<float2*>(&C[(size_t)(row + 8) * Ntot + col]) = v1;
        }
    }
}

// ======================= tensor-core flash attention (unchanged) ============
#define AT_THREADS 352
#define LDKV 40     // K/V smem stride: conflict-free b-frag loads
#define LDP  36     // per-warp P/Q smem stride: conflict-free a-frag loads
#define AT_SMEM ((2 * 64 * LDKV + 11 * 32 * LDP) * 4)   // 71168 B

__global__ __launch_bounds__(AT_THREADS, 1) void attn_mma_kernel(
    const float* __restrict__ qkv, const float* __restrict__ biasP,
    float* __restrict__ out)
{
    extern __shared__ float sm[];
    float* Ks = sm;                 // [64][LDKV]
    float* Vs = sm + 64 * LDKV;     // [64][LDKV]
    const int h   = blockIdx.x;
    const int b   = blockIdx.y;
    const int tid = threadIdx.x;
    const int wid = tid >> 5, lid = tid & 31;
    const int g = lid >> 2, t4 = lid & 3;
    float* Pw = sm + 2 * 64 * LDKV + wid * (32 * LDP);   // warp-private
    const int wm = wid * 32;
    const float* base = qkv + (size_t)b * NTOK * QKVC;
    const float scale = 0.17677669529663687f;

    // ---- stage this warp's Q rows into Pw, then extract scaled tf32 a-frags
#pragma unroll
    for (int i = 0; i < 8; ++i) {
        int f = lid + i * 32;
        int row = f >> 3, c4 = (f & 7) * 4;
        int qrow = wm + row;
        float4 v = make_float4(0.f, 0.f, 0.f, 0.f);
        if (qrow < NTOK)
            v = *reinterpret_cast<const float4*>(base + (size_t)qrow * QKVC + h * HDIM + c4);
        Pw[row * LDP + c4 + 0] = v.x;
        Pw[row * LDP + c4 + 1] = v.y;
        Pw[row * LDP + c4 + 2] = v.z;
        Pw[row * LDP + c4 + 3] = v.w;
    }
    __syncwarp();

    uint32_t qa[2][4][4];
#pragma unroll
    for (int mi = 0; mi < 2; ++mi)
#pragma unroll
        for (int ks = 0; ks < 4; ++ks) {
            const int r0 = (mi * 16 + g) * LDP, r1 = (mi * 16 + 8 + g) * LDP;
            const int k = ks * 8 + t4;
            qa[mi][ks][0] = tf32u(Pw[r0 + k] * scale);
            qa[mi][ks][1] = tf32u(Pw[r1 + k] * scale);
            qa[mi][ks][2] = tf32u(Pw[r0 + k + 4] * scale);
            qa[mi][ks][3] = tf32u(Pw[r1 + k + 4] * scale);
        }

    float o[2][4][4];
#pragma unroll
    for (int mi = 0; mi < 2; ++mi)
#pragma unroll
        for (int n = 0; n < 4; ++n)
#pragma unroll
            for (int q = 0; q < 4; ++q) o[mi][n][q] = 0.f;
    float mrow[2][2] = {{-1e30f, -1e30f}, {-1e30f, -1e30f}};
    float lrow[2][2] = {{0.f, 0.f}, {0.f, 0.f}};

    const float* bp = biasP + ((size_t)h * NPAD + wm) * KPAD;

    for (int ch = 0; ch < 6; ++ch) {
        const int j0 = ch * 64;
        __syncthreads();
        // ---- cooperative K/V chunk load (round to tf32, zero-pad) ---------
#pragma unroll
        for (int i = 0; i < 2; ++i) {
            int f = tid + i * AT_THREADS;
            if (f < 512) {
                int row = f >> 3, c4 = (f & 7) * 4;
                int kr = j0 + row;
                float4 kv = make_float4(0.f, 0.f, 0.f, 0.f);
                float4 vv = make_float4(0.f, 0.f, 0.f, 0.f);
                if (kr < NTOK) {
                    const float* rp = base + (size_t)kr * QKVC + h * HDIM;
                    kv = *reinterpret_cast<const float4*>(rp + CDIM + c4);
                    vv = *reinterpret_cast<const float4*>(rp + 2 * CDIM + c4);
                }
                float4 kr4 = { tf32_rna(kv.x), tf32_rna(kv.y), tf32_rna(kv.z), tf32_rna(kv.w) };
                float4 vr4 = { tf32_rna(vv.x), tf32_rna(vv.y), tf32_rna(vv.z), tf32_rna(vv.w) };
                *reinterpret_cast<float4*>(&Ks[row * LDKV + c4]) = kr4;
                *reinterpret_cast<float4*>(&Vs[row * LDKV + c4]) = vr4;
            }
        }
        __syncthreads();

        // ---- S accumulators initialized from padded bias ------------------
        float c[2][8][4];
#pragma unroll
        for (int mi = 0; mi < 2; ++mi) {
            const float* b0p = bp + (size_t)(mi * 16 + g) * KPAD + j0 + 2 * t4;
            const float* b1p = bp + (size_t)(mi * 16 + 8 + g) * KPAD + j0 + 2 * t4;
#pragma unroll
            for (int ni = 0; ni < 8; ++ni) {
                float2 v0 = *reinterpret_cast<const float2*>(b0p + ni * 8);
                float2 v1 = *reinterpret_cast<const float2*>(b1p + ni * 8);
                c[mi][ni][0] = v0.x; c[mi][ni][1] = v0.y;
                c[mi][ni][2] = v1.x; c[mi][ni][3] = v1.y;
            }
        }
        // ---- S += Q K^T ---------------------------------------------------
#pragma unroll
        for (int ks = 0; ks < 4; ++ks) {
            const int k = ks * 8 + t4;
            uint32_t kb[8][2];
#pragma unroll
            for (int ni = 0; ni < 8; ++ni) {
                kb[ni][0] = __float_as_uint(Ks[(ni * 8 + g) * LDKV + k]);
                kb[ni][1] = __float_as_uint(Ks[(ni * 8 + g) * LDKV + k + 4]);
            }
#pragma unroll
            for (int mi = 0; mi < 2; ++mi)
#pragma unroll
                for (int ni = 0; ni < 8; ++ni)
                    mma_tf32(c[mi][ni], qa[mi][ks], kb[ni]);
        }

        // ---- online softmax ----------------------------------------------
#pragma unroll
        for (int mi = 0; mi < 2; ++mi) {
            float mx0 = c[mi][0][0], mx1 = c[mi][0][2];
#pragma unroll
            for (int ni = 0; ni < 8; ++ni) {
                mx0 = fmaxf(mx0, fmaxf(c[mi][ni][0], c[mi][ni][1]));
                mx1 = fmaxf(mx1, fmaxf(c[mi][ni][2], c[mi][ni][3]));
            }
            mx0 = fmaxf(mx0, __shfl_xor_sync(0xFFFFFFFF, mx0, 1));
            mx0 = fmaxf(mx0, __shfl_xor_sync(0xFFFFFFFF, mx0, 2));
            mx1 = fmaxf(mx1, __shfl_xor_sync(0xFFFFFFFF, mx1, 1));
            mx1 = fmaxf(mx1, __shfl_xor_sync(0xFFFFFFFF, mx1, 2));
            float nm0 = fmaxf(mrow[mi][0], mx0);
            float nm1 = fmaxf(mrow[mi][1], mx1);
            float cr0 = __expf(mrow[mi][0] - nm0);
            float cr1 = __expf(mrow[mi][1] - nm1);
            mrow[mi][0] = nm0; mrow[mi][1] = nm1;
#pragma unroll
            for (int n = 0; n < 4; ++n) {
                o[mi][n][0] *= cr0; o[mi][n][1] *= cr0;
                o[mi][n][2] *= cr1; o[mi][n][3] *= cr1;
            }
            float s0 = 0.f, s1 = 0.f;
#pragma unroll
            for (int ni = 0; ni < 8; ++ni) {
                c[mi][ni][0] = __expf(c[mi][ni][0] - nm0); s0 += c[mi][ni][0];
                c[mi][ni][1] = __expf(c[mi][ni][1] - nm0); s0 += c[mi][ni][1];
                c[mi][ni][2] = __expf(c[mi][ni][2] - nm1); s1 += c[mi][ni][2];
                c[mi][ni][3] = __expf(c[mi][ni][3] - nm1); s1 += c[mi][ni][3];
            }
            s0 += __shfl_xor_sync(0xFFFFFFFF, s0, 1);
            s0 += __shfl_xor_sync(0xFFFFFFFF, s0, 2);
            s1 += __shfl_xor_sync(0xFFFFFFFF, s1, 1);
            s1 += __shfl_xor_sync(0xFFFFFFFF, s1, 2);
            lrow[mi][0] = lrow[mi][0] * cr0 + s0;
            lrow[mi][1] = lrow[mi][1] * cr1 + s1;
        }

        // ---- O += P V : groups of 16 keys via warp-private smem -----------
#pragma unroll
        for (int grp = 0; grp < 4; ++grp) {
#pragma unroll
            for (int mi = 0; mi < 2; ++mi)
#pragma unroll
                for (int q = 0; q < 2; ++q) {
                    const int nt = 2 * grp + q;
                    float2 p0 = { tf32_rna(c[mi][nt][0]), tf32_rna(c[mi][nt][1]) };
                    float2 p1 = { tf32_rna(c[mi][nt][2]), tf32_rna(c[mi][nt][3]) };
                    *reinterpret_cast<float2*>(&Pw[(mi * 16 + g) * LDP + q * 8 + 2 * t4]) = p0;
                    *reinterpret_cast<float2*>(&Pw[(mi * 16 + 8 + g) * LDP + q * 8 + 2 * t4]) = p1;
                }
            __syncwarp();
#pragma unroll
            for (int ks2 = 0; ks2 < 2; ++ks2) {
                uint32_t pa[2][4];
#pragma unroll
                for (int mi = 0; mi < 2; ++mi) {
                    const int r0 = (mi * 16 + g) * LDP, r1 = (mi * 16 + 8 + g) * LDP;
                    const int k = ks2 * 8 + t4;
                    pa[mi][0] = __float_as_uint(Pw[r0 + k]);
                    pa[mi][1] = __float_as_uint(Pw[r1 + k]);
                    pa[mi][2] = __float_as_uint(Pw[r0 + k + 4]);
                    pa[mi][3] = __float_as_uint(Pw[r1 + k + 4]);
                }
                uint32_t vb[4][2];
                const int kr = grp * 16 + ks2 * 8;
#pragma unroll
                for (int n = 0; n < 4; ++n) {
                    vb[n][0] = __float_as_uint(Vs[(kr + t4) * LDKV + n * 8 + g]);
                    vb[n][1] = __float_as_uint(Vs[(kr + t4 + 4) * LDKV + n * 8 + g]);
                }
#pragma unroll
                for (int mi = 0; mi < 2; ++mi)
#pragma unroll
                    for (int n = 0; n < 4; ++n)
                        mma_tf32(o[mi][n], pa[mi], vb[n]);
            }
            __syncwarp();
        }
    }

    // ---- normalize + store (tf32-rounded for proj GEMM input) -------------
#pragma unroll
    for (int mi = 0; mi < 2; ++mi) {
        const float i0 = 1.f / lrow[mi][0];
        const float i1 = 1.f / lrow[mi][1];
        const int r0 = wm + mi * 16 + g;
        const int r1 = r0 + 8;
        if (r0 < NTOK) {
            float* op = out + ((size_t)b * NTOK + r0) * CDIM + h * HDIM + 2 * t4;
#pragma unroll
            for (int n = 0; n < 4; ++n) {
                float2 v = { tf32_rna(o[mi][n][0] * i0), tf32_rna(o[mi][n][1] * i0) };
                *reinterpret_cast<float2*>(op + n * 8) = v;
            }
        }
        if (r1 < NTOK) {
            float* op = out + ((size_t)b * NTOK + r1) * CDIM + h * HDIM + 2 * t4;
#pragma unroll
            for (int n = 0; n < 4; ++n) {
                float2 v = { tf32_rna(o[mi][n][2] * i1), tf32_rna(o[mi][n][3] * i1) };
                *reinterpret_cast<float2*>(op + n * 8) = v;
            }
        }
    }
}

// ---------------- launch ------------------------------------------------------
extern "C" void kernel_launch(void* const* d_in, const int* in_sizes, int n_in,
                              void* d_out, int out_size)
{
    const float* x       = (const float*)d_in[0];
    const float* qkv_w   = (const float*)d_in[1];
    const float* qkv_b   = (const float*)d_in[2];
    const float* proj_w  = (const float*)d_in[3];
    const float* proj_b  = (const float*)d_in[4];
    const float* bt      = (const float*)d_in[5];
    const int*   ridx    = (const int*)d_in[6];
    float*       out     = (float*)d_out;

    void *p_qkv, *p_att, *p_bias, *p_xr, *p_wqt, *p_wpt;
    cudaGetSymbolAddress(&p_qkv,  g_qkv);
    cudaGetSymbolAddress(&p_att,  g_att);
    cudaGetSymbolAddress(&p_bias, g_bias);
    cudaGetSymbolAddress(&p_xr,   g_xr);
    cudaGetSymbolAddress(&p_wqt,  g_wqt);
    cudaGetSymbolAddress(&p_wpt,  g_wpt);
    float* qkv  = (float*)p_qkv;
    float* att  = (float*)p_att;
    float* bias = (float*)p_bias;
    float* xr   = (float*)p_xr;
    float* wqt  = (float*)p_wqt;
    float* wpt  = (float*)p_wpt;

    cudaFuncSetAttribute(mma_gemm_kernel,
                         cudaFuncAttributeMaxDynamicSharedMemorySize, GSM_TOT);
    cudaFuncSetAttribute(attn_mma_kernel,
                         cudaFuncAttributeMaxDynamicSharedMemorySize, AT_SMEM);

    // 0) prep: tf32-round x; transpose+round weights; expand padded bias
    {
        int n4 = MROWS * CDIM / 4;
        round_tf32_kernel<<<(n4 + 255) / 256, 256>>>(x, xr, n4);
        transpose_round_kernel<<<dim3(QKVC / 32, CDIM / 32), dim3(32, 8)>>>(qkv_w, wqt, CDIM, QKVC);
        transpose_round_kernel<<<dim3(CDIM / 32, CDIM / 32), dim3(32, 8)>>>(proj_w, wpt, CDIM, CDIM);
        int total = NHEADS * NPAD * KPAD;
        bias_expand_pad_kernel<<<(total + 255) / 256, 256>>>(bt, ridx, bias);
    }

    // 1) QKV projection (mma.sync tf32, 256x128 CTA tile)
    mma_gemm_kernel<<<dim3(QKVC / 128, MROWS / 256), 256, GSM_TOT>>>(xr, wqt, qkv_b, qkv, QKVC);

    // 2) tensor-core flash attention (QK^T + bias + softmax + PV)
    attn_mma_kernel<<<dim3(NHEADS, NWIN), AT_THREADS, AT_SMEM>>>(qkv, bias, att);

    // 3) output projection (mma.sync tf32, 256x128 CTA tile)
    mma_gemm_kernel<<<dim3(CDIM / 128, MROWS / 256), 256, GSM_TOT>>>(att, wpt, proj_b, out, CDIM);
}